// round 3
// baseline (speedup 1.0000x reference)
#include <cuda_runtime.h>
#include <cuda_bf16.h>

#define NJ   32
#define TPB  128
#define IN_PAD  37   // 36 data floats + 1 pad (odd stride -> conflict-free LDS)
#define OUT_PAD 13   // 12 data floats + 1 pad

__global__ void __launch_bounds__(TPB)
fk32_kernel(const float* __restrict__ angles,
            const float* __restrict__ offs,
            float* __restrict__ out,
            int batch)
{
    __shared__ float s_in [TPB * IN_PAD];   // 18,944 B
    __shared__ float s_out[TPB * OUT_PAD];  //  6,656 B

    const int t  = threadIdx.x;
    const int B0 = blockIdx.x * TPB;
    const int b  = B0 + t;

    // H36M parent table; constant indexing under full unroll -> folded.
    const int par[NJ] = {-1,0,1,2,3,4,0,6,7,8,9,0,11,12,13,14,12,16,17,18,
                         19,20,19,22,12,24,25,26,27,28,27,30};
    // Joints whose rotation is consumed by a child (leaves skip R update).
    const bool isp[NJ] = {1,1,1,1,1,0,1,1,1,1,0,1,1,1,1,0,
                          1,1,1,1,1,0,1,0,1,1,1,1,1,0,1,0};

    // FK state; constant indices after unroll -> register-allocated by liveness
    // (max ~2-3 rotations live across group boundaries).
    float R[NJ][9];
    float P[NJ][3];

    #pragma unroll
    for (int g = 0; g < 8; ++g) {
        // ================= phase 1: coalesced GMEM -> SMEM ==================
        // Block needs angles[B0..B0+127][g*36 .. g*36+35]  (128 rows x 144B,
        // row stride 1152B). idx = t + k*128 walks it fully coalesced.
        #pragma unroll
        for (int k = 0; k < 36; ++k) {
            int idx = t + k * TPB;            // 0..4607
            int c   = idx / 36;               // batch-in-block
            int off = idx - c * 36;           // float within group record
            int bb  = B0 + c;
            if (bb >= batch) bb = batch - 1;  // safe clamp (exact tiles here)
            s_in[c * IN_PAD + off] =
                angles[(size_t)bb * 288 + g * 36 + off];
        }
        __syncthreads();

        // ================= phase 2: per-thread FK for joints 4g..4g+3 =======
        float a[36];
        #pragma unroll
        for (int k = 0; k < 36; ++k) a[k] = s_in[t * IN_PAD + k];

        #pragma unroll
        for (int jj = 0; jj < 4; ++jj) {
            const int j = g * 4 + jj;
            const float* Aj = &a[jj * 9];
            if (j == 0) {
                #pragma unroll
                for (int q = 0; q < 9; ++q) R[0][q] = Aj[q];
                P[0][0] = 0.f; P[0][1] = 0.f; P[0][2] = 0.f;
            } else {
                const int p = par[j];
                // pos[j] = offsets[j] (row-vec) @ rot[p] + pos[p]
                const float o0 = __ldg(&offs[j*3+0]);
                const float o1 = __ldg(&offs[j*3+1]);
                const float o2 = __ldg(&offs[j*3+2]);
                #pragma unroll
                for (int l = 0; l < 3; ++l) {
                    P[j][l] = fmaf(o0, R[p][0*3+l],
                              fmaf(o1, R[p][1*3+l],
                              fmaf(o2, R[p][2*3+l], P[p][l])));
                }
                // rot[j] = A[j] @ rot[p]  (skip for leaves - never consumed)
                if (isp[j]) {
                    #pragma unroll
                    for (int i = 0; i < 3; ++i) {
                        #pragma unroll
                        for (int l = 0; l < 3; ++l) {
                            R[j][i*3+l] = fmaf(Aj[i*3+0], R[p][0*3+l],
                                          fmaf(Aj[i*3+1], R[p][1*3+l],
                                               Aj[i*3+2] * R[p][2*3+l]));
                        }
                    }
                }
            }
        }

        // stage this group's 12 position floats in smem
        {
            float* row = &s_out[t * OUT_PAD];
            #pragma unroll
            for (int jj = 0; jj < 4; ++jj) {
                const int j = g * 4 + jj;
                row[jj*3+0] = P[j][0];
                row[jj*3+1] = P[j][1];
                row[jj*3+2] = P[j][2];
            }
        }
        __syncthreads();

        // ================= phase 3: coalesced SMEM -> GMEM ==================
        // out[B0..B0+127][g*12 .. g*12+11]  (128 rows x 48B, row stride 384B)
        #pragma unroll
        for (int k = 0; k < 12; ++k) {
            int idx = t + k * TPB;            // 0..1535
            int c   = idx / 12;
            int off = idx - c * 12;
            int bb  = B0 + c;
            if (bb < batch)
                out[(size_t)bb * 96 + g * 12 + off] =
                    s_out[c * OUT_PAD + off];
        }
        // no extra barrier needed: next loop's load phase is fenced by the
        // __syncthreads() after it before anyone re-reads s_in, and s_out is
        // only rewritten after the next sync as well.
    }
}

extern "C" void kernel_launch(void* const* d_in, const int* in_sizes, int n_in,
                              void* d_out, int out_size)
{
    const float* angles = (const float*)d_in[0];
    const float* offs   = (const float*)d_in[1];
    float* out          = (float*)d_out;

    int batch  = in_sizes[0] / (NJ * 9);          // 262144
    int blocks = (batch + TPB - 1) / TPB;         // 2048

    fk32_kernel<<<blocks, TPB>>>(angles, offs, out, batch);
}